// round 7
// baseline (speedup 1.0000x reference)
#include <cuda_runtime.h>
#include <cuda_bf16.h>
#include <math.h>

// ---------------------------------------------------------------------------
// MnistAdditionModule: LeNet (16384 digit images) -> per-digit log-softmax
//                      -> circuit over n1+n2 sums  => out [4096, 199] fp32
// ---------------------------------------------------------------------------

#define N_IMAGES 16384
#define BATCH    4096

typedef unsigned long long u64;

// packed-f32x2 helpers (sm_100+ double-rate fp32 path; PTX-only)
__device__ __forceinline__ u64 pack_dup(float v) {
    u64 r; asm("mov.b64 %0, {%1, %1};" : "=l"(r) : "f"(v)); return r;
}
__device__ __forceinline__ void fma2(u64& c, u64 a, u64 b) {
    asm("fma.rn.f32x2 %0, %1, %2, %0;" : "+l"(c) : "l"(a), "l"(b));
}
__device__ __forceinline__ float2 unpk(u64 v) {
    float2 f; asm("mov.b64 {%0, %1}, %2;" : "=f"(f.x), "=f"(f.y) : "l"(v)); return f;
}

// intermediate buffers (static device memory; no allocations allowed)
__device__ float g_out1[N_IMAGES * 6 * 12 * 12];   // conv1+pool+relu
__device__ float g_out2[N_IMAGES * 256];           // conv2+pool+relu (flattened)
__device__ float g_lp  [N_IMAGES * 10];            // per-image log-probs

// ---------------------------------------------------------------------------
// K1: conv1 (1->6, 5x5) + bias + maxpool2 + relu.  One block per image.
// Input plane stored PRE-DUPLICATED as u64 in smem: window reads are single
// LDS.64, no per-use dup MOVs in the inner loop.
// ---------------------------------------------------------------------------
__global__ void conv1_kernel(const float* __restrict__ images,
                             const float* __restrict__ w,
                             const float* __restrict__ b) {
    __shared__ u64 img2[784];                 // (v,v) per pixel
    __shared__ __align__(8) float ws2[300];   // 3 pairs x 25 x 2 (interleaved)
    __shared__ float bs[6];
    int n = blockIdx.x;
    const float* im = images + n * 784;
    for (int i = threadIdx.x; i < 784; i += blockDim.x) img2[i] = pack_dup(im[i]);
    if (threadIdx.x < 150) {
        int ch = threadIdx.x / 25, ij = threadIdx.x % 25;
        ws2[((ch >> 1) * 25 + ij) * 2 + (ch & 1)] = w[threadIdx.x];
    }
    if (threadIdx.x < 6) bs[threadIdx.x] = b[threadIdx.x];
    __syncthreads();

    int t = threadIdx.x;
    if (t >= 144) return;
    int oh = t / 12, ow = t - oh * 12;

    // 6x6 dup'd input window (one LDS.64 each)
    u64 win2[6][6];
#pragma unroll
    for (int i = 0; i < 6; i++)
#pragma unroll
        for (int j = 0; j < 6; j++)
            win2[i][j] = img2[(2 * oh + i) * 28 + (2 * ow + j)];

    float* out = g_out1 + n * 864 + t;
#pragma unroll
    for (int p = 0; p < 3; p++) {               // channel pair
        u64 a00 = 0, a01 = 0, a10 = 0, a11 = 0;
        const u64* wp = (const u64*)&ws2[p * 50];
#pragma unroll
        for (int i = 0; i < 5; i++)
#pragma unroll
            for (int j = 0; j < 5; j++) {
                u64 wv = wp[i * 5 + j];         // (w_ch_even, w_ch_odd)
                fma2(a00, win2[i][j],         wv);
                fma2(a01, win2[i][j + 1],     wv);
                fma2(a10, win2[i + 1][j],     wv);
                fma2(a11, win2[i + 1][j + 1], wv);
            }
        float2 f00 = unpk(a00), f01 = unpk(a01), f10 = unpk(a10), f11 = unpk(a11);
        float me = fmaxf(fmaxf(f00.x, f01.x), fmaxf(f10.x, f11.x)) + bs[2 * p];
        float mo = fmaxf(fmaxf(f00.y, f01.y), fmaxf(f10.y, f11.y)) + bs[2 * p + 1];
        out[(2 * p)     * 144] = fmaxf(me, 0.f);
        out[(2 * p + 1) * 144] = fmaxf(mo, 0.f);
    }
}

// ---------------------------------------------------------------------------
// K2: conv2 (6->16, 5x5 on 12x12) + bias + maxpool2 + relu.
// 128 threads = 2 images x (16 pooled positions x 2 channel-quads).
// Each thread: 4 channels (= 2 f32x2-packed pairs) at one pooled position.
// Input planes pre-duplicated as u64 in smem (LDS.64 window reads, no MOVs).
// ---------------------------------------------------------------------------
__global__ void conv2_kernel(const float* __restrict__ w,
                             const float* __restrict__ b) {
    __shared__ u64 in2[1728];                  // 2 x 6 x 12 x 12, dup'd
    __shared__ __align__(8) float ws2[2400];   // 8 pairs x 6 ic x 25 x 2
    __shared__ float bs[16];
    int n0 = blockIdx.x * 2;
    for (int i = threadIdx.x; i < 1728; i += 128)
        in2[i] = pack_dup(g_out1[n0 * 864 + i]);
    for (int i = threadIdx.x; i < 2400; i += 128) {
        int ch = i / 150, r = i - ch * 150;
        int ic = r / 25, ij = r - ic * 25;
        ws2[(((ch >> 1) * 6 + ic) * 25 + ij) * 2 + (ch & 1)] = w[i];
    }
    if (threadIdx.x < 16) bs[threadIdx.x] = b[threadIdx.x];
    __syncthreads();

    int t = threadIdx.x;
    int img = t >> 6, local = t & 63;
    int pos = local & 15, cg = local >> 4;     // cg: channel-quad 0..3
    int oh = pos >> 2, ow = pos & 3;
    const u64* inp = in2 + img * 864;

    u64 acc[2][4] = {};                        // [pair-in-quad][a00,a01,a10,a11]
    for (int ic = 0; ic < 6; ic++) {
        u64 win2[6][6];
#pragma unroll
        for (int i = 0; i < 6; i++)
#pragma unroll
            for (int j = 0; j < 6; j++)
                win2[i][j] = inp[ic * 144 + (2 * oh + i) * 12 + (2 * ow + j)];
#pragma unroll
        for (int q = 0; q < 2; q++) {
            int p = cg * 2 + q;
            const u64* wp = (const u64*)&ws2[((p * 6 + ic) * 25) * 2];
#pragma unroll
            for (int i = 0; i < 5; i++)
#pragma unroll
                for (int j = 0; j < 5; j++) {
                    u64 wv = wp[i * 5 + j];
                    fma2(acc[q][0], win2[i][j],         wv);
                    fma2(acc[q][1], win2[i][j + 1],     wv);
                    fma2(acc[q][2], win2[i + 1][j],     wv);
                    fma2(acc[q][3], win2[i + 1][j + 1], wv);
                }
        }
    }
    float* out = g_out2 + (n0 + img) * 256;
#pragma unroll
    for (int q = 0; q < 2; q++) {
        float2 f0 = unpk(acc[q][0]), f1 = unpk(acc[q][1]);
        float2 f2 = unpk(acc[q][2]), f3 = unpk(acc[q][3]);
        int che = cg * 4 + 2 * q;
        float me = fmaxf(fmaxf(f0.x, f1.x), fmaxf(f2.x, f3.x)) + bs[che];
        float mo = fmaxf(fmaxf(f0.y, f1.y), fmaxf(f2.y, f3.y)) + bs[che + 1];
        out[che * 16 + pos]       = fmaxf(me, 0.f);
        out[(che + 1) * 16 + pos] = fmaxf(mo, 0.f);
    }
}

// ---------------------------------------------------------------------------
// K3: fc1(256->120)+relu, fc2(120->84)+relu, fc3(84->10), log_softmax.
// (reverted to the 309-us R5 version: scalar 4x4 register tiles)
// ---------------------------------------------------------------------------
#define FC_SMEM_FLOATS (30976 + 10200 + 840 + 120 + 84 + 16 + 8192 + 3840)
#define FC_SMEM_BYTES  (FC_SMEM_FLOATS * 4)

__global__ void fc_kernel(const float* __restrict__ w1, const float* __restrict__ b1,
                          const float* __restrict__ w2, const float* __restrict__ b2,
                          const float* __restrict__ w3, const float* __restrict__ b3) {
    extern __shared__ float sm[];
    float* s_w1 = sm;              // [256][121] k-major, padded
    float* s_w2 = s_w1 + 30976;    // [120][85]  k-major, padded
    float* s_w3 = s_w2 + 10200;    // [84][10]   k-major
    float* s_b1 = s_w3 + 840;      // 120
    float* s_b2 = s_b1 + 120;      // 84
    float* s_b3 = s_b2 + 84;       // 16
    float* s_x  = s_b3 + 16;       // [32][256]; later aliased by h2, z
    float* s_h1 = s_x  + 8192;     // [32][120]
    float* s_h2 = s_x;             // [32][84]  (x dead after fc1)
    float* s_z  = s_x + 4096;      // [32][10]

    int t = threadIdx.x;           // 256 threads
    for (int i = t; i < 30720; i += 256) {
        int j = i >> 8, k = i & 255;                 // w1 is [120][256]
        s_w1[k * 121 + j] = w1[i];
    }
    for (int i = t; i < 10080; i += 256) {
        int j = i / 120, k = i - j * 120;
        s_w2[k * 85 + j] = w2[i];
    }
    for (int i = t; i < 840; i += 256) {
        int j = i / 84, k = i - j * 84;
        s_w3[k * 10 + j] = w3[i];
    }
    if (t < 120) s_b1[t] = b1[t];
    if (t < 84)  s_b2[t] = b2[t];
    if (t < 16)  s_b3[t] = (t < 10) ? b3[t] : 0.f;

    int n0 = blockIdx.x * 32;
    for (int i = t; i < 8192; i += 256) s_x[i] = g_out2[n0 * 256 + i];
    __syncthreads();

    int gg = t >> 5, jj = t & 31;   // warp = one image-quad -> x reads broadcast

    // fc1: 4 images x 4 outputs per thread (j = jj + 30u), jj < 30
    if (jj < 30) {
        float acc[4][4];
#pragma unroll
        for (int u = 0; u < 4; u++) {
            float bv = s_b1[jj + 30 * u];
#pragma unroll
            for (int gi = 0; gi < 4; gi++) acc[gi][u] = bv;
        }
        const float* xb = s_x + gg * 1024;
#pragma unroll 4
        for (int k = 0; k < 256; k++) {
            float x0 = xb[k], x1 = xb[k + 256], x2 = xb[k + 512], x3 = xb[k + 768];
            const float* wr = s_w1 + k * 121 + jj;
            float wa = wr[0], wb = wr[30], wc = wr[60], wd = wr[90];
            acc[0][0] = fmaf(x0, wa, acc[0][0]); acc[0][1] = fmaf(x0, wb, acc[0][1]);
            acc[0][2] = fmaf(x0, wc, acc[0][2]); acc[0][3] = fmaf(x0, wd, acc[0][3]);
            acc[1][0] = fmaf(x1, wa, acc[1][0]); acc[1][1] = fmaf(x1, wb, acc[1][1]);
            acc[1][2] = fmaf(x1, wc, acc[1][2]); acc[1][3] = fmaf(x1, wd, acc[1][3]);
            acc[2][0] = fmaf(x2, wa, acc[2][0]); acc[2][1] = fmaf(x2, wb, acc[2][1]);
            acc[2][2] = fmaf(x2, wc, acc[2][2]); acc[2][3] = fmaf(x2, wd, acc[2][3]);
            acc[3][0] = fmaf(x3, wa, acc[3][0]); acc[3][1] = fmaf(x3, wb, acc[3][1]);
            acc[3][2] = fmaf(x3, wc, acc[3][2]); acc[3][3] = fmaf(x3, wd, acc[3][3]);
        }
#pragma unroll
        for (int gi = 0; gi < 4; gi++)
#pragma unroll
            for (int u = 0; u < 4; u++)
                s_h1[(gg * 4 + gi) * 120 + jj + 30 * u] = fmaxf(acc[gi][u], 0.f);
    }
    __syncthreads();

    // fc2: 4 images x 4 outputs (j = jj + 21u), jj < 21. Writes alias x region.
    if (jj < 21) {
        float acc[4][4];
#pragma unroll
        for (int u = 0; u < 4; u++) {
            float bv = s_b2[jj + 21 * u];
#pragma unroll
            for (int gi = 0; gi < 4; gi++) acc[gi][u] = bv;
        }
        const float* xb = s_h1 + gg * 480;
#pragma unroll 4
        for (int k = 0; k < 120; k++) {
            float x0 = xb[k], x1 = xb[k + 120], x2 = xb[k + 240], x3 = xb[k + 360];
            const float* wr = s_w2 + k * 85 + jj;
            float wa = wr[0], wb = wr[21], wc = wr[42], wd = wr[63];
            acc[0][0] = fmaf(x0, wa, acc[0][0]); acc[0][1] = fmaf(x0, wb, acc[0][1]);
            acc[0][2] = fmaf(x0, wc, acc[0][2]); acc[0][3] = fmaf(x0, wd, acc[0][3]);
            acc[1][0] = fmaf(x1, wa, acc[1][0]); acc[1][1] = fmaf(x1, wb, acc[1][1]);
            acc[1][2] = fmaf(x1, wc, acc[1][2]); acc[1][3] = fmaf(x1, wd, acc[1][3]);
            acc[2][0] = fmaf(x2, wa, acc[2][0]); acc[2][1] = fmaf(x2, wb, acc[2][1]);
            acc[2][2] = fmaf(x2, wc, acc[2][2]); acc[2][3] = fmaf(x2, wd, acc[2][3]);
            acc[3][0] = fmaf(x3, wa, acc[3][0]); acc[3][1] = fmaf(x3, wb, acc[3][1]);
            acc[3][2] = fmaf(x3, wc, acc[3][2]); acc[3][3] = fmaf(x3, wd, acc[3][3]);
        }
#pragma unroll
        for (int gi = 0; gi < 4; gi++)
#pragma unroll
            for (int u = 0; u < 4; u++)
                s_h2[(gg * 4 + gi) * 84 + jj + 21 * u] = fmaxf(acc[gi][u], 0.f);
    }
    __syncthreads();

    // fc3: 32 img x 10 outputs = 320 dots over 84 (tiny)
    for (int o = t; o < 320; o += 256) {
        int g = o / 10, j = o - g * 10;
        const float* xp = s_h2 + g * 84;
        float acc = s_b3[j];
#pragma unroll
        for (int k = 0; k < 84; k++) acc = fmaf(xp[k], s_w3[k * 10 + j], acc);
        s_z[o] = acc;
    }
    __syncthreads();

    // log_softmax per image
    if (t < 32) {
        const float* z = s_z + t * 10;
        float m = -1e30f;
#pragma unroll
        for (int i = 0; i < 10; i++) m = fmaxf(m, z[i]);
        float s = 0.f;
#pragma unroll
        for (int i = 0; i < 10; i++) s += __expf(z[i] - m);
        float lse = __logf(s) + m;
        float* out = g_lp + (n0 + t) * 10;
#pragma unroll
        for (int i = 0; i < 10; i++) out[i] = z[i] - lse;
    }
}

// ---------------------------------------------------------------------------
// K4: circuit. out[s] = log( sum_i p1[i]*p2[s-i] ) + m1 + m2  (exact
// linear-space equivalent of the grouped logsumexp).
// (reverted to the 309-us R5 version: divergent bounds beat padded loop)
// ---------------------------------------------------------------------------
__global__ void circuit_kernel(float* __restrict__ out) {
    __shared__ float p1[100], p2[100];
    __shared__ float msum[2];
    int b = blockIdx.x;
    const float* lp = g_lp + b * 40;
    int t = threadIdx.x;   // 256 threads

    if (t == 0) {
        float m0 = -1e30f, m1 = -1e30f, m2 = -1e30f, m3 = -1e30f;
#pragma unroll
        for (int i = 0; i < 10; i++) {
            m0 = fmaxf(m0, lp[i]);
            m1 = fmaxf(m1, lp[10 + i]);
            m2 = fmaxf(m2, lp[20 + i]);
            m3 = fmaxf(m3, lp[30 + i]);
        }
        msum[0] = m0 + m1;
        msum[1] = m2 + m3;
    }
    __syncthreads();
    if (t < 100) {
        p1[t] = __expf(lp[t / 10] + lp[10 + t % 10] - msum[0]);
    } else if (t < 200) {
        int k = t - 100;
        p2[k] = __expf(lp[20 + k / 10] + lp[30 + k % 10] - msum[1]);
    }
    __syncthreads();
    if (t < 199) {
        int lo = max(0, t - 99), hi = min(99, t);
        float s = 0.f;
        for (int i = lo; i <= hi; i++) s = fmaf(p1[i], p2[t - i], s);
        out[b * 199 + t] = __logf(s) + msum[0] + msum[1];
    }
}

// ---------------------------------------------------------------------------
extern "C" void kernel_launch(void* const* d_in, const int* in_sizes, int n_in,
                              void* d_out, int out_size) {
    const float* images = (const float*)d_in[0];
    const float* c1w    = (const float*)d_in[1];
    const float* c1b    = (const float*)d_in[2];
    const float* c2w    = (const float*)d_in[3];
    const float* c2b    = (const float*)d_in[4];
    const float* f1w    = (const float*)d_in[5];
    const float* f1b    = (const float*)d_in[6];
    const float* f2w    = (const float*)d_in[7];
    const float* f2b    = (const float*)d_in[8];
    const float* f3w    = (const float*)d_in[9];
    const float* f3b    = (const float*)d_in[10];
    float* out = (float*)d_out;

    cudaFuncSetAttribute(fc_kernel, cudaFuncAttributeMaxDynamicSharedMemorySize,
                         FC_SMEM_BYTES);

    conv1_kernel<<<N_IMAGES, 160>>>(images, c1w, c1b);
    conv2_kernel<<<N_IMAGES / 2, 128>>>(c2w, c2b);
    fc_kernel<<<N_IMAGES / 32, 256, FC_SMEM_BYTES>>>(f1w, f1b, f2w, f2b, f3w, f3b);
    circuit_kernel<<<BATCH, 256>>>(out);
}

// round 8
// speedup vs baseline: 1.1374x; 1.1374x over previous
#include <cuda_runtime.h>
#include <cuda_bf16.h>
#include <math.h>

// ---------------------------------------------------------------------------
// MnistAdditionModule: LeNet (16384 digit images) -> per-digit log-softmax
//                      -> circuit over n1+n2 sums  => out [4096, 199] fp32
// ---------------------------------------------------------------------------

#define N_IMAGES 16384
#define BATCH    4096

typedef unsigned long long u64;

// packed-f32x2 helpers (sm_100+ double-rate fp32 path; PTX-only)
__device__ __forceinline__ u64 pack_dup(float v) {
    u64 r; asm("mov.b64 %0, {%1, %1};" : "=l"(r) : "f"(v)); return r;
}
__device__ __forceinline__ u64 pack2(float a, float b) {
    u64 r; asm("mov.b64 %0, {%1, %2};" : "=l"(r) : "f"(a), "f"(b)); return r;
}
__device__ __forceinline__ void fma2(u64& c, u64 a, u64 b) {
    asm("fma.rn.f32x2 %0, %1, %2, %0;" : "+l"(c) : "l"(a), "l"(b));
}
__device__ __forceinline__ float2 unpk(u64 v) {
    float2 f; asm("mov.b64 {%0, %1}, %2;" : "=f"(f.x), "=f"(f.y) : "l"(v)); return f;
}

// intermediate buffers (static device memory; no allocations allowed)
__device__ float g_out1[N_IMAGES * 6 * 12 * 12];   // conv1+pool+relu
__device__ float g_out2[N_IMAGES * 256];           // conv2+pool+relu (flattened)
__device__ float g_lp  [N_IMAGES * 10];            // per-image log-probs
__device__ __align__(16) float g_w1T[256 * 120];   // fc1 weights, k-major
__device__ __align__(16) float g_w2T[120 * 84];    // fc2 weights, k-major

// ---------------------------------------------------------------------------
// K0: prep — transpose fc weights to k-major global (tiny, runs once/graph).
// ---------------------------------------------------------------------------
__global__ void prep_kernel(const float* __restrict__ w1,
                            const float* __restrict__ w2) {
    int t = blockIdx.x * 256 + threadIdx.x;
    for (int i = t; i < 30720; i += gridDim.x * 256) {
        int j = i >> 8, k = i & 255;               // w1 is [120][256]
        g_w1T[k * 120 + j] = w1[i];
    }
    for (int i = t; i < 10080; i += gridDim.x * 256) {
        int j = i / 120, k = i - j * 120;          // w2 is [84][120]
        g_w2T[k * 84 + j] = w2[i];
    }
}

// ---------------------------------------------------------------------------
// K1: conv1 (1->6, 5x5) + bias + maxpool2 + relu.  One block per image.
// (R5 version: LDS.32 window + dup MOVs — dup on idle ALU pipe beats 2x LDS bytes)
// ---------------------------------------------------------------------------
__global__ void conv1_kernel(const float* __restrict__ images,
                             const float* __restrict__ w,
                             const float* __restrict__ b) {
    __shared__ float img[784];
    __shared__ __align__(8) float ws2[300];   // 3 pairs x 25 x 2 (interleaved)
    __shared__ float bs[6];
    int n = blockIdx.x;
    const float* im = images + n * 784;
    for (int i = threadIdx.x; i < 784; i += blockDim.x) img[i] = im[i];
    if (threadIdx.x < 150) {
        int ch = threadIdx.x / 25, ij = threadIdx.x % 25;
        ws2[((ch >> 1) * 25 + ij) * 2 + (ch & 1)] = w[threadIdx.x];
    }
    if (threadIdx.x < 6) bs[threadIdx.x] = b[threadIdx.x];
    __syncthreads();

    int t = threadIdx.x;
    if (t >= 144) return;
    int oh = t / 12, ow = t - oh * 12;

    u64 win2[6][6];
#pragma unroll
    for (int i = 0; i < 6; i++)
#pragma unroll
        for (int j = 0; j < 6; j++)
            win2[i][j] = pack_dup(img[(2 * oh + i) * 28 + (2 * ow + j)]);

    float* out = g_out1 + n * 864 + t;
#pragma unroll
    for (int p = 0; p < 3; p++) {               // channel pair
        u64 a00 = 0, a01 = 0, a10 = 0, a11 = 0;
        const u64* wp = (const u64*)&ws2[p * 50];
#pragma unroll
        for (int i = 0; i < 5; i++)
#pragma unroll
            for (int j = 0; j < 5; j++) {
                u64 wv = wp[i * 5 + j];         // (w_ch_even, w_ch_odd)
                fma2(a00, win2[i][j],         wv);
                fma2(a01, win2[i][j + 1],     wv);
                fma2(a10, win2[i + 1][j],     wv);
                fma2(a11, win2[i + 1][j + 1], wv);
            }
        float2 f00 = unpk(a00), f01 = unpk(a01), f10 = unpk(a10), f11 = unpk(a11);
        float me = fmaxf(fmaxf(f00.x, f01.x), fmaxf(f10.x, f11.x)) + bs[2 * p];
        float mo = fmaxf(fmaxf(f00.y, f01.y), fmaxf(f10.y, f11.y)) + bs[2 * p + 1];
        out[(2 * p)     * 144] = fmaxf(me, 0.f);
        out[(2 * p + 1) * 144] = fmaxf(mo, 0.f);
    }
}

// ---------------------------------------------------------------------------
// K2: conv2 (6->16, 5x5 on 12x12) + bias + maxpool2 + relu.  (R5 version)
// ---------------------------------------------------------------------------
__global__ void conv2_kernel(const float* __restrict__ w,
                             const float* __restrict__ b) {
    __shared__ float in[1728];                 // 2 x 6 x 12 x 12
    __shared__ __align__(8) float ws2[2400];   // 8 pairs x 6 ic x 25 x 2
    __shared__ float bs[16];
    int n0 = blockIdx.x * 2;
    for (int i = threadIdx.x; i < 1728; i += 128) in[i] = g_out1[n0 * 864 + i];
    for (int i = threadIdx.x; i < 2400; i += 128) {
        int ch = i / 150, r = i - ch * 150;
        int ic = r / 25, ij = r - ic * 25;
        ws2[(((ch >> 1) * 6 + ic) * 25 + ij) * 2 + (ch & 1)] = w[i];
    }
    if (threadIdx.x < 16) bs[threadIdx.x] = b[threadIdx.x];
    __syncthreads();

    int t = threadIdx.x;
    int img = t >> 6, local = t & 63;
    int pos = local & 15, cg = local >> 4;     // cg: channel-quad 0..3
    int oh = pos >> 2, ow = pos & 3;
    const float* inp = in + img * 864;

    u64 acc[2][4] = {};                        // [pair-in-quad][a00,a01,a10,a11]
    for (int ic = 0; ic < 6; ic++) {
        u64 win2[6][6];
#pragma unroll
        for (int i = 0; i < 6; i++)
#pragma unroll
            for (int j = 0; j < 6; j++)
                win2[i][j] = pack_dup(inp[ic * 144 + (2 * oh + i) * 12 + (2 * ow + j)]);
#pragma unroll
        for (int q = 0; q < 2; q++) {
            int p = cg * 2 + q;
            const u64* wp = (const u64*)&ws2[((p * 6 + ic) * 25) * 2];
#pragma unroll
            for (int i = 0; i < 5; i++)
#pragma unroll
                for (int j = 0; j < 5; j++) {
                    u64 wv = wp[i * 5 + j];
                    fma2(acc[q][0], win2[i][j],         wv);
                    fma2(acc[q][1], win2[i][j + 1],     wv);
                    fma2(acc[q][2], win2[i + 1][j],     wv);
                    fma2(acc[q][3], win2[i + 1][j + 1], wv);
                }
        }
    }
    float* out = g_out2 + (n0 + img) * 256;
#pragma unroll
    for (int q = 0; q < 2; q++) {
        float2 f0 = unpk(acc[q][0]), f1 = unpk(acc[q][1]);
        float2 f2 = unpk(acc[q][2]), f3 = unpk(acc[q][3]);
        int che = cg * 4 + 2 * q;
        float me = fmaxf(fmaxf(f0.x, f1.x), fmaxf(f2.x, f3.x)) + bs[che];
        float mo = fmaxf(fmaxf(f0.y, f1.y), fmaxf(f2.y, f3.y)) + bs[che + 1];
        out[che * 16 + pos]       = fmaxf(me, 0.f);
        out[(che + 1) * 16 + pos] = fmaxf(mo, 0.f);
    }
}

// ---------------------------------------------------------------------------
// K3 v2: fc stack, 64 images/block (256 blocks), 256 threads, ~104 KB smem
// -> 2 CTAs/SM (16 warps). Activations live in smem as IMAGE-PAIR u64
// (f32x2 SIMD over images); weights stream from k-major global via one
// LDG.128 per k per thread (j-quad).  Per k: 4 uniform LDS.64 + 1 LDG.128
// + 4 dup-MOV + 16 FFMA2 = 25 slots / 32 MACs.
// ---------------------------------------------------------------------------
// smem (u64 units where noted):  x2[256][33]u64  h1[120][33]u64 (x region
// reused by h2[84][33]u64 after fc1)  + w3/b/z scalars.
#define FC_X2_U64   (256 * 33)
#define FC_H1_U64   (120 * 33)
#define FC_TAIL_F   (840 + 120 + 84 + 16 + 640)
#define FC_SMEM_BYTES (FC_X2_U64 * 8 + FC_H1_U64 * 8 + FC_TAIL_F * 4)

__global__ void fc_kernel(const float* __restrict__ b1,
                          const float* __restrict__ b2,
                          const float* __restrict__ w3, const float* __restrict__ b3) {
    extern __shared__ __align__(16) char smraw[];
    u64*   s_x2 = (u64*)smraw;                 // [256][33] image-pair acts
    u64*   s_h1 = s_x2 + FC_X2_U64;            // [120][33]
    u64*   s_h2 = s_x2;                        // [84][33], aliases dead x
    float* s_w3 = (float*)(s_h1 + FC_H1_U64);  // [84][10] k-major
    float* s_b1 = s_w3 + 840;                  // 120
    float* s_b2 = s_b1 + 120;                  // 84
    float* s_b3 = s_b2 + 84;                   // 16
    float* s_z  = s_b3 + 16;                   // [64][10]

    int t = threadIdx.x;                       // 256 threads
    int n0 = blockIdx.x * 64;

    // fill x2: pair p = images (n0+2p, n0+2p+1), k-major rows, stride 33
    for (int idx = t; idx < 32 * 256; idx += 256) {
        int p = idx >> 8, k = idx & 255;
        float a = g_out2[(n0 + 2 * p) * 256 + k];
        float c = g_out2[(n0 + 2 * p + 1) * 256 + k];
        s_x2[k * 33 + p] = pack2(a, c);
    }
    for (int i = t; i < 840; i += 256) {
        int j = i / 84, k = i - j * 84;
        s_w3[k * 10 + j] = w3[i];
    }
    if (t < 120) s_b1[t] = b1[t];
    if (t < 84)  s_b2[t] = b2[t];
    if (t < 16)  s_b3[t] = (t < 10) ? b3[t] : 0.f;
    __syncthreads();

    int w = t >> 5, jj = t & 31;
    int pg = w * 4;                            // this warp's 4 image pairs

    // fc1: 8 images (4 pairs) x 4 outputs (j-quad 4jj..4jj+3); jj < 30
    if (jj < 30) {
        u64 acc[4][4];
#pragma unroll
        for (int u = 0; u < 4; u++) {
            u64 bv = pack_dup(s_b1[4 * jj + u]);
            acc[0][u] = bv; acc[1][u] = bv; acc[2][u] = bv; acc[3][u] = bv;
        }
#pragma unroll 2
        for (int k = 0; k < 256; k++) {
            const u64* xr = s_x2 + k * 33 + pg;
            u64 x0 = xr[0], x1 = xr[1], x2 = xr[2], x3 = xr[3];
            float4 wq = *(const float4*)(g_w1T + k * 120 + 4 * jj);
            u64 w0 = pack_dup(wq.x), w1 = pack_dup(wq.y);
            u64 w2 = pack_dup(wq.z), w3v = pack_dup(wq.w);
            fma2(acc[0][0], x0, w0); fma2(acc[1][0], x1, w0);
            fma2(acc[2][0], x2, w0); fma2(acc[3][0], x3, w0);
            fma2(acc[0][1], x0, w1); fma2(acc[1][1], x1, w1);
            fma2(acc[2][1], x2, w1); fma2(acc[3][1], x3, w1);
            fma2(acc[0][2], x0, w2); fma2(acc[1][2], x1, w2);
            fma2(acc[2][2], x2, w2); fma2(acc[3][2], x3, w2);
            fma2(acc[0][3], x0, w3v); fma2(acc[1][3], x1, w3v);
            fma2(acc[2][3], x2, w3v); fma2(acc[3][3], x3, w3v);
        }
#pragma unroll
        for (int i = 0; i < 4; i++)
#pragma unroll
            for (int u = 0; u < 4; u++) {
                float2 f = unpk(acc[i][u]);
                s_h1[(4 * jj + u) * 33 + pg + i] =
                    pack2(fmaxf(f.x, 0.f), fmaxf(f.y, 0.f));
            }
    }
    __syncthreads();

    // fc2: 8 images x 4 outputs (j-quad 4jj..4jj+3); jj < 21
    if (jj < 21) {
        u64 acc[4][4];
#pragma unroll
        for (int u = 0; u < 4; u++) {
            u64 bv = pack_dup(s_b2[4 * jj + u]);
            acc[0][u] = bv; acc[1][u] = bv; acc[2][u] = bv; acc[3][u] = bv;
        }
#pragma unroll 2
        for (int k = 0; k < 120; k++) {
            const u64* xr = s_h1 + k * 33 + pg;
            u64 x0 = xr[0], x1 = xr[1], x2 = xr[2], x3 = xr[3];
            float4 wq = *(const float4*)(g_w2T + k * 84 + 4 * jj);
            u64 w0 = pack_dup(wq.x), w1 = pack_dup(wq.y);
            u64 w2 = pack_dup(wq.z), w3v = pack_dup(wq.w);
            fma2(acc[0][0], x0, w0); fma2(acc[1][0], x1, w0);
            fma2(acc[2][0], x2, w0); fma2(acc[3][0], x3, w0);
            fma2(acc[0][1], x0, w1); fma2(acc[1][1], x1, w1);
            fma2(acc[2][1], x2, w1); fma2(acc[3][1], x3, w1);
            fma2(acc[0][2], x0, w2); fma2(acc[1][2], x1, w2);
            fma2(acc[2][2], x2, w2); fma2(acc[3][2], x3, w2);
            fma2(acc[0][3], x0, w3v); fma2(acc[1][3], x1, w3v);
            fma2(acc[2][3], x2, w3v); fma2(acc[3][3], x3, w3v);
        }
#pragma unroll
        for (int i = 0; i < 4; i++)
#pragma unroll
            for (int u = 0; u < 4; u++) {
                float2 f = unpk(acc[i][u]);
                s_h2[(4 * jj + u) * 33 + pg + i] =
                    pack2(fmaxf(f.x, 0.f), fmaxf(f.y, 0.f));
            }
    }
    __syncthreads();

    // fc3: 64 img x 10 outputs = 640 dots over 84 (tiny)
    const float* h2f = (const float*)s_h2;
    for (int o = t; o < 640; o += 256) {
        int g = o / 10, j = o - g * 10;
        int p = g >> 1, lane = g & 1;
        float acc = s_b3[j];
#pragma unroll
        for (int k = 0; k < 84; k++)
            acc = fmaf(h2f[(k * 33 + p) * 2 + lane], s_w3[k * 10 + j], acc);
        s_z[g * 10 + j] = acc;
    }
    __syncthreads();

    // log_softmax per image
    if (t < 64) {
        const float* z = s_z + t * 10;
        float m = -1e30f;
#pragma unroll
        for (int i = 0; i < 10; i++) m = fmaxf(m, z[i]);
        float s = 0.f;
#pragma unroll
        for (int i = 0; i < 10; i++) s += __expf(z[i] - m);
        float lse = __logf(s) + m;
        float* out = g_lp + (n0 + t) * 10;
#pragma unroll
        for (int i = 0; i < 10; i++) out[i] = z[i] - lse;
    }
}

// ---------------------------------------------------------------------------
// K4: circuit (R5 version). out[s] = log(sum_i p1[i]*p2[s-i]) + m1 + m2.
// ---------------------------------------------------------------------------
__global__ void circuit_kernel(float* __restrict__ out) {
    __shared__ float p1[100], p2[100];
    __shared__ float msum[2];
    int b = blockIdx.x;
    const float* lp = g_lp + b * 40;
    int t = threadIdx.x;   // 256 threads

    if (t == 0) {
        float m0 = -1e30f, m1 = -1e30f, m2 = -1e30f, m3 = -1e30f;
#pragma unroll
        for (int i = 0; i < 10; i++) {
            m0 = fmaxf(m0, lp[i]);
            m1 = fmaxf(m1, lp[10 + i]);
            m2 = fmaxf(m2, lp[20 + i]);
            m3 = fmaxf(m3, lp[30 + i]);
        }
        msum[0] = m0 + m1;
        msum[1] = m2 + m3;
    }
    __syncthreads();
    if (t < 100) {
        p1[t] = __expf(lp[t / 10] + lp[10 + t % 10] - msum[0]);
    } else if (t < 200) {
        int k = t - 100;
        p2[k] = __expf(lp[20 + k / 10] + lp[30 + k % 10] - msum[1]);
    }
    __syncthreads();
    if (t < 199) {
        int lo = max(0, t - 99), hi = min(99, t);
        float s = 0.f;
        for (int i = lo; i <= hi; i++) s = fmaf(p1[i], p2[t - i], s);
        out[b * 199 + t] = __logf(s) + msum[0] + msum[1];
    }
}

// ---------------------------------------------------------------------------
extern "C" void kernel_launch(void* const* d_in, const int* in_sizes, int n_in,
                              void* d_out, int out_size) {
    const float* images = (const float*)d_in[0];
    const float* c1w    = (const float*)d_in[1];
    const float* c1b    = (const float*)d_in[2];
    const float* c2w    = (const float*)d_in[3];
    const float* c2b    = (const float*)d_in[4];
    const float* f1w    = (const float*)d_in[5];
    const float* f1b    = (const float*)d_in[6];
    const float* f2w    = (const float*)d_in[7];
    const float* f2b    = (const float*)d_in[8];
    const float* f3w    = (const float*)d_in[9];
    const float* f3b    = (const float*)d_in[10];
    float* out = (float*)d_out;

    cudaFuncSetAttribute(fc_kernel, cudaFuncAttributeMaxDynamicSharedMemorySize,
                         FC_SMEM_BYTES);

    prep_kernel<<<30, 256>>>(f1w, f2w);
    conv1_kernel<<<N_IMAGES, 160>>>(images, c1w, c1b);
    conv2_kernel<<<N_IMAGES / 2, 128>>>(c2w, c2b);
    fc_kernel<<<N_IMAGES / 64, 256, FC_SMEM_BYTES>>>(f1b, f2b, f3w, f3b);
    circuit_kernel<<<BATCH, 256>>>(out);
}